// round 7
// baseline (speedup 1.0000x reference)
#include <cuda_runtime.h>
#include <cstdint>

// YOLO layer: x (64, 255, 44, 44) f32 -> out (64, 5808, 85) f32.
//   out[b, a*1936 + s, c] = f(x[b, a*85 + c, s])
//   c==0:(sig+gx)*8  c==1:(sig+gy)*8  c==2:exp*aw  c==3:exp*ah  c>=4:sig
//
// R7: persistent CTAs (304 = 2/SM), grid-stride over 3072 tiles, DOUBLE-
// buffered smem (2 x 43,520 B dynamic). TMA bulk write of tile i overlaps
// LDG read phase of tile i+1 (wait_group.read 1 gates buffer reuse).
// Reads: warp-per-channel LDG.128, all 6 float4 loads front-batched (MLP=6).
// Sigmoid: 4-instruction approx (FMUL, MUFU.EX2, FADD, MUFU.RCP).

#define G44    44
#define GG     1936
#define CH     85
#define NA     3
#define TS     128
#define NTHR   512
#define NWARP  16
#define NTILES 3072            // 192 (b,a) * 16 s-tiles
#define TILE_F (TS * CH)       // floats per buffer
#define NCTA   304             // 2 per SM x 152 SMs

__constant__ float c_aw[NA] = {10.0f, 16.0f, 33.0f};   // scaled_anchor*STRIDE
__constant__ float c_ah[NA] = {13.0f, 30.0f, 23.0f};

__device__ __forceinline__ float sig_(float v) {
    float e;
    asm("ex2.approx.ftz.f32 %0, %1;" : "=f"(e) : "f"(v * -1.442695041f));
    float r;
    asm("rcp.approx.ftz.f32 %0, %1;" : "=f"(r) : "f"(1.0f + e));
    return r;
}

__device__ __forceinline__ float exp_(float v) {
    float e;
    asm("ex2.approx.ftz.f32 %0, %1;" : "=f"(e) : "f"(v * 1.442695041f));
    return e;
}

extern __shared__ float smbuf[];   // 2 * TILE_F floats = 87,040 B

__global__ __launch_bounds__(NTHR, 2)
void yolo_kernel(const float* __restrict__ x, float* __restrict__ out) {
    const int warp = threadIdx.x >> 5;
    const int lane = threadIdx.x & 31;
    const int sl   = lane << 2;                 // spatial offset within tile
    const int nk   = (warp < 5) ? 6 : 5;        // channels this thread owns

    int it = 0;
    for (int t = blockIdx.x; t < NTILES; t += NCTA, ++it) {
        float* sm = smbuf + (it & 1) * TILE_F;

        const int ba = t >> 4;                  // b*NA + a
        const int a  = ba % NA;
        const int s0 = (t & 15) << 7;
        const int valid = min(TS, GG - s0);     // 128, or 16 on last s-tile

        // gate: bulk copy issued 2 iterations ago (same buffer) must be done
        if (threadIdx.x == 0)
            asm volatile("cp.async.bulk.wait_group.read 1;" ::: "memory");
        __syncthreads();

        if (sl < valid) {
            const float* __restrict__ ib =
                x + (size_t)ba * (CH * GG) + (s0 + sl);
            float* __restrict__ row = sm + sl * CH;

            // ---- front-batch all channel loads (independent LDG.128) ----
            float4 v[6];
            #pragma unroll
            for (int k = 0; k < 6; k++)
                if (k < 5 || warp < 5)
                    v[k] = *(const float4*)(ib + (size_t)(warp + k * NWARP) * GG);

            // ---- k = 0: special channels live only here (warp-uniform) ----
            {
                float t0, t1, t2, t3;
                if (warp >= 4) {
                    t0 = sig_(v[0].x); t1 = sig_(v[0].y);
                    t2 = sig_(v[0].z); t3 = sig_(v[0].w);
                } else if (warp == 0) {
                    const int s  = s0 + sl;
                    const int gx = s - (s / G44) * G44;   // s%4==0, 44%4==0
                    t0 = (sig_(v[0].x) + (float)(gx + 0)) * 8.0f;
                    t1 = (sig_(v[0].y) + (float)(gx + 1)) * 8.0f;
                    t2 = (sig_(v[0].z) + (float)(gx + 2)) * 8.0f;
                    t3 = (sig_(v[0].w) + (float)(gx + 3)) * 8.0f;
                } else if (warp == 1) {
                    const float fy = (float)((s0 + sl) / G44);
                    t0 = (sig_(v[0].x) + fy) * 8.0f;
                    t1 = (sig_(v[0].y) + fy) * 8.0f;
                    t2 = (sig_(v[0].z) + fy) * 8.0f;
                    t3 = (sig_(v[0].w) + fy) * 8.0f;
                } else if (warp == 2) {
                    const float aw = c_aw[a];
                    t0 = exp_(v[0].x) * aw; t1 = exp_(v[0].y) * aw;
                    t2 = exp_(v[0].z) * aw; t3 = exp_(v[0].w) * aw;
                } else {                              // warp == 3
                    const float ah = c_ah[a];
                    t0 = exp_(v[0].x) * ah; t1 = exp_(v[0].y) * ah;
                    t2 = exp_(v[0].z) * ah; t3 = exp_(v[0].w) * ah;
                }
                row[0 * CH + warp] = t0;
                row[1 * CH + warp] = t1;
                row[2 * CH + warp] = t2;
                row[3 * CH + warp] = t3;
            }

            // ---- k = 1..5: pure sigmoid ----
            #pragma unroll
            for (int k = 1; k < 6; k++) {
                if (k < nk) {
                    const int ch = warp + k * NWARP;
                    row[0 * CH + ch] = sig_(v[k].x);
                    row[1 * CH + ch] = sig_(v[k].y);
                    row[2 * CH + ch] = sig_(v[k].z);
                    row[3 * CH + ch] = sig_(v[k].w);
                }
            }
        }

        __syncthreads();

        // ---- commit bulk write, do NOT wait (overlaps next tile's reads) ----
        if (threadIdx.x == 0) {
            uint32_t saddr;
            asm volatile("{ .reg .u64 t; cvta.to.shared.u64 t, %1; cvt.u32.u64 %0, t; }"
                         : "=r"(saddr) : "l"(sm));
            float* gptr = out + ((size_t)ba * GG + s0) * CH;   // 16B-aligned
            const uint32_t bytes = (uint32_t)(valid * CH * 4); // mult of 16

            asm volatile("fence.proxy.async.shared::cta;" ::: "memory");
            asm volatile("cp.async.bulk.global.shared::cta.bulk_group [%0], [%1], %2;"
                         :: "l"(gptr), "r"(saddr), "r"(bytes) : "memory");
            asm volatile("cp.async.bulk.commit_group;" ::: "memory");
        }
    }

    // drain before CTA exit (smem must stay alive for pending TMA reads)
    if (threadIdx.x == 0)
        asm volatile("cp.async.bulk.wait_group.read 0;" ::: "memory");
}

extern "C" void kernel_launch(void* const* d_in, const int* in_sizes, int n_in,
                              void* d_out, int out_size) {
    const float* x = (const float*)d_in[0];
    float* out = (float*)d_out;

    static const size_t shmem = 2 * TILE_F * sizeof(float);   // 87,040 B
    cudaFuncSetAttribute(yolo_kernel,
                         cudaFuncAttributeMaxDynamicSharedMemorySize,
                         (int)shmem);
    yolo_kernel<<<NCTA, NTHR, shmem>>>(x, out);
}